// round 1
// baseline (speedup 1.0000x reference)
#include <cuda_runtime.h>
#include <math.h>
#include <stdint.h>

// Problem dims (fixed by the dataset)
#define T_STEPS   4
#define NODE_NUM  10000
#define NUM_NODES 50000
#define E_DIM     256
#define H_DIM     512   // 2*E
#define C_DIM     128
#define U_DIM     256   // 2*C
#define ROWS      (T_STEPS * NODE_NUM)   // 40000
#define LN_EPS    1e-5f

// ---------------- scratch (__device__ globals; no allocs allowed) ------------
__device__ float g_S [(size_t)T_STEPS * NUM_NODES * E_DIM]; // scatter table (only active rows touched)
__device__ float g_A0[(size_t)ROWS * E_DIM];                // LN(inp) gathered
__device__ float g_H1[(size_t)ROWS * H_DIM];                // gelu(A0@W1_d+b1)
__device__ float g_C [(size_t)ROWS * C_DIM];                // H1@W2_d+b2
__device__ float g_G [(size_t)ROWS * C_DIM];                // LN(g_C)
__device__ float g_H2[(size_t)ROWS * U_DIM];                // gelu(G@W1_u+b1u)

// ---------------- kernel 1: zero touched rows of the scatter table ----------
__global__ void k_zero_rows(const int* __restrict__ idx) {
    int r = blockIdx.x;                       // gathered row 0..ROWS-1
    int t = r / NODE_NUM;
    int node = idx[r];
    float4* p = (float4*)&g_S[((size_t)t * NUM_NODES + node) * E_DIM];
    p[threadIdx.x] = make_float4(0.f, 0.f, 0.f, 0.f);   // 64 threads x float4 = 256 floats
}

// ---------------- kernel 2: scatter-add x rows into table -------------------
__global__ void k_scatter(const float* __restrict__ x, const int* __restrict__ idx) {
    int r = blockIdx.x;
    int t = r / NODE_NUM;
    int node = idx[r];
    float* dst = &g_S[((size_t)t * NUM_NODES + node) * E_DIM];
    const float* src = x + (size_t)r * E_DIM;
    atomicAdd(&dst[threadIdx.x], src[threadIdx.x]);
}

// ---------------- block reduction helper ------------------------------------
// Computes mean/rstd of per-thread value v across blockDim.x (multiple of 32, <=256)
__device__ __forceinline__ void ln_stats(float v, int width, float& mu, float& rs) {
    __shared__ float s1[8], s2[8];
    __shared__ float s_mu, s_rs;
    float a = v, b = v * v;
    #pragma unroll
    for (int o = 16; o > 0; o >>= 1) {
        a += __shfl_down_sync(0xffffffffu, a, o);
        b += __shfl_down_sync(0xffffffffu, b, o);
    }
    int w = threadIdx.x >> 5;
    if ((threadIdx.x & 31) == 0) { s1[w] = a; s2[w] = b; }
    __syncthreads();
    if (threadIdx.x == 0) {
        int nw = blockDim.x >> 5;
        float sa = 0.f, sb = 0.f;
        for (int i = 0; i < nw; i++) { sa += s1[i]; sb += s2[i]; }
        float m = sa / (float)width;
        float var = sb / (float)width - m * m;
        s_mu = m;
        s_rs = rsqrtf(var + LN_EPS);
    }
    __syncthreads();
    mu = s_mu; rs = s_rs;
}

// ---------------- kernel 3: gather + add batched_x + LayerNorm(E) -----------
__global__ void k_gather_ln(const float* __restrict__ bx, const int* __restrict__ idx,
                            const float* __restrict__ scale, const float* __restrict__ bias) {
    int r = blockIdx.x;
    int t = r / NODE_NUM;
    int node = idx[r];
    int e = threadIdx.x;       // 256 threads
    float v = g_S[((size_t)t * NUM_NODES + node) * E_DIM + e]
            + bx[(size_t)node * E_DIM + e];
    float mu, rs;
    ln_stats(v, E_DIM, mu, rs);
    g_A0[(size_t)r * E_DIM + e] = (v - mu) * rs * scale[e] + bias[e];
}

// ---------------- kernel: plain LayerNorm over width W ----------------------
template<int W>
__global__ void k_ln(const float* __restrict__ src, float* __restrict__ dst,
                     const float* __restrict__ scale, const float* __restrict__ bias) {
    int r = blockIdx.x;
    int e = threadIdx.x;       // W threads
    float v = src[(size_t)r * W + e];
    float mu, rs;
    ln_stats(v, W, mu, rs);
    dst[(size_t)r * W + e] = (v - mu) * rs * scale[e] + bias[e];
}

// ---------------- tiled SGEMM 128x128x8, 256 threads, 8x8/thread ------------
// C[M,N] = A[M,K] @ B[K,N] + bias[N], optional exact GELU.
// Requires: K % 8 == 0, N % 128 == 0. M arbitrary (guarded).
template<bool GELU>
__global__ void __launch_bounds__(256) sgemm(const float* __restrict__ A,
                                             const float* __restrict__ B,
                                             const float* __restrict__ bias,
                                             float* __restrict__ Cout,
                                             int M, int N, int K) {
    __shared__ float As[8][128];
    __shared__ float Bs[8][128];
    const int tx = threadIdx.x;
    const int bm = blockIdx.y * 128;
    const int bn = blockIdx.x * 128;

    const int tm = (tx >> 4) * 8;          // 0..120
    const int tn = (tx & 15) * 8;          // 0..120

    const int row_a = tx >> 1;             // 0..127
    const int col_a = (tx & 1) * 4;        // 0 or 4
    const int row_b = tx >> 5;             // 0..7
    const int col_b = (tx & 31) * 4;       // 0..124

    float acc[8][8];
    #pragma unroll
    for (int i = 0; i < 8; i++)
        #pragma unroll
        for (int j = 0; j < 8; j++) acc[i][j] = 0.f;

    for (int k0 = 0; k0 < K; k0 += 8) {
        float4 av = make_float4(0.f, 0.f, 0.f, 0.f);
        if (bm + row_a < M)
            av = *(const float4*)(A + (size_t)(bm + row_a) * K + k0 + col_a);
        As[col_a + 0][row_a] = av.x;
        As[col_a + 1][row_a] = av.y;
        As[col_a + 2][row_a] = av.z;
        As[col_a + 3][row_a] = av.w;
        *(float4*)&Bs[row_b][col_b] =
            *(const float4*)(B + (size_t)(k0 + row_b) * N + bn + col_b);
        __syncthreads();

        #pragma unroll
        for (int kk = 0; kk < 8; kk++) {
            float a[8], b[8];
            #pragma unroll
            for (int i = 0; i < 8; i++) a[i] = As[kk][tm + i];
            #pragma unroll
            for (int j = 0; j < 8; j++) b[j] = Bs[kk][tn + j];
            #pragma unroll
            for (int i = 0; i < 8; i++)
                #pragma unroll
                for (int j = 0; j < 8; j++)
                    acc[i][j] += a[i] * b[j];
        }
        __syncthreads();
    }

    #pragma unroll
    for (int i = 0; i < 8; i++) {
        int row = bm + tm + i;
        if (row >= M) continue;
        #pragma unroll
        for (int j = 0; j < 8; j++) {
            int col = bn + tn + j;
            float v = acc[i][j] + bias[col];
            if (GELU) v = 0.5f * v * (1.0f + erff(v * 0.70710678118654752f));
            Cout[(size_t)row * N + col] = v;
        }
    }
}

// ---------------- launcher ---------------------------------------------------
extern "C" void kernel_launch(void* const* d_in, const int* in_sizes, int n_in,
                              void* d_out, int out_size) {
    (void)in_sizes; (void)n_in; (void)out_size;
    const float* x          = (const float*)d_in[0];   // [40000,256]
    const float* batched_x  = (const float*)d_in[1];   // [50000,256]
    const int*   indices    = (const int*)  d_in[2];   // [4,10000]
    const float* ln_d_scale = (const float*)d_in[3];   // [256]
    const float* ln_d_bias  = (const float*)d_in[4];   // [256]
    const float* W1_d       = (const float*)d_in[5];   // [256,512]
    const float* b1_d       = (const float*)d_in[6];   // [512]
    const float* W2_d       = (const float*)d_in[7];   // [512,128]
    const float* b2_d       = (const float*)d_in[8];   // [128]
    const float* ln_u_scale = (const float*)d_in[9];   // [128]
    const float* ln_u_bias  = (const float*)d_in[10];  // [128]
    const float* W1_u       = (const float*)d_in[11];  // [128,256]
    const float* b1_u       = (const float*)d_in[12];  // [256]
    const float* W2_u       = (const float*)d_in[13];  // [256,256]
    const float* b2_u       = (const float*)d_in[14];  // [256]
    float* out = (float*)d_out;                        // [40000,256]

    float *pS, *pA0, *pH1, *pC, *pG, *pH2;
    cudaGetSymbolAddress((void**)&pS,  g_S);
    cudaGetSymbolAddress((void**)&pA0, g_A0);
    cudaGetSymbolAddress((void**)&pH1, g_H1);
    cudaGetSymbolAddress((void**)&pC,  g_C);
    cudaGetSymbolAddress((void**)&pG,  g_G);
    cudaGetSymbolAddress((void**)&pH2, g_H2);
    (void)pS; (void)pA0; (void)pH1; (void)pC; (void)pG; (void)pH2;

    // 1) zero only the rows the scatter will touch
    k_zero_rows<<<ROWS, 64>>>(indices);
    // 2) scatter-add x into per-step node table
    k_scatter<<<ROWS, 256>>>(x, indices);
    // 3) gather + broadcast-add + LN(E)  -> A0
    k_gather_ln<<<ROWS, 256>>>(batched_x, indices, ln_d_scale, ln_d_bias);
    // 4) H1 = gelu(A0 @ W1_d + b1_d)        [40000,512]
    sgemm<true ><<<dim3(H_DIM / 128, (ROWS + 127) / 128), 256>>>(pA0, W1_d, b1_d, pH1, ROWS, H_DIM, E_DIM);
    // 5) C  = H1 @ W2_d + b2_d              [40000,128]
    sgemm<false><<<dim3(C_DIM / 128, (ROWS + 127) / 128), 256>>>(pH1, W2_d, b2_d, pC, ROWS, C_DIM, H_DIM);
    // 6) G  = LN(C)                          [40000,128]
    k_ln<C_DIM><<<ROWS, C_DIM>>>(pC, pG, ln_u_scale, ln_u_bias);
    // 7) H2 = gelu(G @ W1_u + b1_u)          [40000,256]
    sgemm<true ><<<dim3(U_DIM / 128, (ROWS + 127) / 128), 256>>>(pG, W1_u, b1_u, pH2, ROWS, U_DIM, C_DIM);
    // 8) out = H2 @ W2_u + b2_u              [40000,256]
    sgemm<false><<<dim3(E_DIM / 128, (ROWS + 127) / 128), 256>>>(pH2, W2_u, b2_u, out, ROWS, E_DIM, U_DIM);
}

// round 5
// speedup vs baseline: 2.0885x; 2.0885x over previous
#include <cuda_runtime.h>
#include <cuda_bf16.h>
#include <math.h>
#include <stdint.h>

// ---------------- problem dims (fixed) ----------------
#define T_STEPS   4
#define NODE_NUM  10000
#define NUM_NODES 50000
#define E_DIM     256
#define H_DIM     512
#define C_DIM     128
#define U_DIM     256
#define ROWS      (T_STEPS * NODE_NUM)   // 40000
#define LN_EPS    1e-5f
#define MBLK      ((ROWS + 127) / 128)   // 313

typedef __nv_bfloat16 bf16;

// ---------------- scratch (__device__ globals) ----------------
__device__ float g_S[(size_t)T_STEPS * NUM_NODES * E_DIM];
// split-bf16 activations (hi/lo pairs)
__device__ bf16 g_A0h[(size_t)ROWS * E_DIM], g_A0l[(size_t)ROWS * E_DIM];
__device__ bf16 g_H1h[(size_t)ROWS * H_DIM], g_H1l[(size_t)ROWS * H_DIM];
__device__ bf16 g_Ch [(size_t)ROWS * C_DIM], g_Cl [(size_t)ROWS * C_DIM];
__device__ bf16 g_Gh [(size_t)ROWS * C_DIM], g_Gl [(size_t)ROWS * C_DIM];
__device__ bf16 g_H2h[(size_t)ROWS * U_DIM], g_H2l[(size_t)ROWS * U_DIM];
// transposed + split weights, [N][K]
__device__ bf16 g_w1dh[H_DIM * E_DIM], g_w1dl[H_DIM * E_DIM];
__device__ bf16 g_w2dh[C_DIM * H_DIM], g_w2dl[C_DIM * H_DIM];
__device__ bf16 g_w1uh[U_DIM * C_DIM], g_w1ul[U_DIM * C_DIM];
__device__ bf16 g_w2uh[E_DIM * U_DIM], g_w2ul[E_DIM * U_DIM];

// ---------------- helpers ----------------
static __device__ __forceinline__ uint32_t smem_u32(const void* p) {
    uint32_t a;
    asm("{ .reg .u64 t; cvta.to.shared.u64 t, %1; cvt.u32.u64 %0, t; }" : "=r"(a) : "l"(p));
    return a;
}

static __device__ __forceinline__ void split2(float a, float b,
                                              __nv_bfloat162& h, __nv_bfloat162& l) {
    h = __floats2bfloat162_rn(a, b);
    float2 hf = __bfloat1622float2(h);
    l = __floats2bfloat162_rn(a - hf.x, b - hf.y);
}

static __device__ __forceinline__ float gelu_exact(float v) {
    return 0.5f * v * (1.0f + erff(v * 0.70710678118654752f));
}

#define CP_ASYNC16(dst, src, sz) \
    asm volatile("cp.async.cg.shared.global [%0], [%1], 16, %2;" \
                 :: "r"(dst), "l"(src), "r"(sz) : "memory")
#define CP_ASYNC16_U(dst, src) \
    asm volatile("cp.async.cg.shared.global [%0], [%1], 16;" \
                 :: "r"(dst), "l"(src) : "memory")
#define CP_COMMIT() asm volatile("cp.async.commit_group;" ::: "memory")
#define CP_WAIT2()  asm volatile("cp.async.wait_group 2;" ::: "memory")

#define LDMATRIX_X4(r0, r1, r2, r3, addr) \
    asm volatile("ldmatrix.sync.aligned.m8n8.x4.shared.b16 {%0,%1,%2,%3}, [%4];" \
                 : "=r"(r0), "=r"(r1), "=r"(r2), "=r"(r3) : "r"(addr))

#define MMA16816(c0, c1, c2, c3, a0, a1, a2, a3, b0, b1) \
    asm volatile("mma.sync.aligned.m16n8k16.row.col.f32.bf16.bf16.f32 " \
                 "{%0,%1,%2,%3}, {%4,%5,%6,%7}, {%8,%9}, {%0,%1,%2,%3};" \
                 : "+f"(c0), "+f"(c1), "+f"(c2), "+f"(c3) \
                 : "r"(a0), "r"(a1), "r"(a2), "r"(a3), "r"(b0), "r"(b1))

// ---------------- prep: transpose + bf16-split weights ----------------
// W[k*N+n] -> hi/lo[n*K+k]
__global__ void k_wsplit(const float* __restrict__ W, bf16* __restrict__ hi,
                         bf16* __restrict__ lo, int K, int N) {
    int i = blockIdx.x * 256 + threadIdx.x;
    if (i >= N * K) return;
    int n = i / K, k = i % K;
    float v = W[k * N + n];
    bf16 h = __float2bfloat16_rn(v);
    hi[i] = h;
    lo[i] = __float2bfloat16_rn(v - __bfloat162float(h));
}

// ---------------- front-end ----------------
__global__ void k_zero_rows(const int* __restrict__ idx) {
    int r = blockIdx.x * 8 + (threadIdx.x >> 5);
    if (r >= ROWS) return;
    int lane = threadIdx.x & 31;
    int t = r / NODE_NUM;
    int node = idx[r];
    float4* p = (float4*)&g_S[((size_t)t * NUM_NODES + node) * E_DIM];
    float4 z = make_float4(0.f, 0.f, 0.f, 0.f);
    p[lane] = z; p[lane + 32] = z;
}

__global__ void k_scatter(const float* __restrict__ x, const int* __restrict__ idx) {
    int r = blockIdx.x * 8 + (threadIdx.x >> 5);
    if (r >= ROWS) return;
    int lane = threadIdx.x & 31;
    int t = r / NODE_NUM;
    int node = idx[r];
    float* dst = &g_S[((size_t)t * NUM_NODES + node) * E_DIM];
    const float* src = x + (size_t)r * E_DIM;
    #pragma unroll
    for (int j = 0; j < 8; j++)
        atomicAdd(dst + lane + j * 32, src[lane + j * 32]);
}

// gather + broadcast-add + LN(256) -> split bf16 A0
__global__ void k_gather_ln(const float* __restrict__ bx, const int* __restrict__ idx,
                            const float* __restrict__ sc, const float* __restrict__ bi) {
    int r = blockIdx.x * 8 + (threadIdx.x >> 5);
    if (r >= ROWS) return;
    int lane = threadIdx.x & 31;
    int t = r / NODE_NUM;
    int node = idx[r];
    const float* srow = &g_S[((size_t)t * NUM_NODES + node) * E_DIM];
    const float* brow = bx + (size_t)node * E_DIM;
    float4 a0 = *(const float4*)(srow + lane * 4);
    float4 a1 = *(const float4*)(srow + 128 + lane * 4);
    float4 b0 = *(const float4*)(brow + lane * 4);
    float4 b1 = *(const float4*)(brow + 128 + lane * 4);
    float v[8] = { a0.x + b0.x, a0.y + b0.y, a0.z + b0.z, a0.w + b0.w,
                   a1.x + b1.x, a1.y + b1.y, a1.z + b1.z, a1.w + b1.w };
    float s1 = 0.f, s2 = 0.f;
    #pragma unroll
    for (int j = 0; j < 8; j++) { s1 += v[j]; s2 += v[j] * v[j]; }
    #pragma unroll
    for (int o = 16; o > 0; o >>= 1) {
        s1 += __shfl_xor_sync(0xffffffffu, s1, o);
        s2 += __shfl_xor_sync(0xffffffffu, s2, o);
    }
    float mu = s1 * (1.f / 256.f);
    float rs = rsqrtf(s2 * (1.f / 256.f) - mu * mu + LN_EPS);
    #pragma unroll
    for (int half = 0; half < 2; half++) {
        #pragma unroll
        for (int j = 0; j < 2; j++) {
            int c = half * 128 + lane * 4 + j * 2;
            float o0 = (v[half * 4 + j * 2 + 0] - mu) * rs * sc[c]     + bi[c];
            float o1 = (v[half * 4 + j * 2 + 1] - mu) * rs * sc[c + 1] + bi[c + 1];
            __nv_bfloat162 h, l;
            split2(o0, o1, h, l);
            *(__nv_bfloat162*)&g_A0h[(size_t)r * E_DIM + c] = h;
            *(__nv_bfloat162*)&g_A0l[(size_t)r * E_DIM + c] = l;
        }
    }
}

// LN over width 128 on split input -> split output
__global__ void k_ln128(const bf16* __restrict__ hiS, const bf16* __restrict__ loS,
                        bf16* __restrict__ hiD, bf16* __restrict__ loD,
                        const float* __restrict__ sc, const float* __restrict__ bi) {
    int r = blockIdx.x * 8 + (threadIdx.x >> 5);
    if (r >= ROWS) return;
    int lane = threadIdx.x & 31;
    const bf16* ph = hiS + (size_t)r * C_DIM;
    const bf16* pl = loS + (size_t)r * C_DIM;
    float v[4];
    #pragma unroll
    for (int j = 0; j < 2; j++) {
        __nv_bfloat162 h = *(const __nv_bfloat162*)(ph + lane * 4 + j * 2);
        __nv_bfloat162 l = *(const __nv_bfloat162*)(pl + lane * 4 + j * 2);
        float2 hf = __bfloat1622float2(h), lf = __bfloat1622float2(l);
        v[j * 2 + 0] = hf.x + lf.x;
        v[j * 2 + 1] = hf.y + lf.y;
    }
    float s1 = 0.f, s2 = 0.f;
    #pragma unroll
    for (int j = 0; j < 4; j++) { s1 += v[j]; s2 += v[j] * v[j]; }
    #pragma unroll
    for (int o = 16; o > 0; o >>= 1) {
        s1 += __shfl_xor_sync(0xffffffffu, s1, o);
        s2 += __shfl_xor_sync(0xffffffffu, s2, o);
    }
    float mu = s1 * (1.f / 128.f);
    float rs = rsqrtf(s2 * (1.f / 128.f) - mu * mu + LN_EPS);
    #pragma unroll
    for (int j = 0; j < 2; j++) {
        int c = lane * 4 + j * 2;
        float o0 = (v[j * 2 + 0] - mu) * rs * sc[c]     + bi[c];
        float o1 = (v[j * 2 + 1] - mu) * rs * sc[c + 1] + bi[c + 1];
        __nv_bfloat162 h, l;
        split2(o0, o1, h, l);
        *(__nv_bfloat162*)&hiD[(size_t)r * C_DIM + c] = h;
        *(__nv_bfloat162*)&loD[(size_t)r * C_DIM + c] = l;
    }
}

// ---------------- mma.sync bf16 GEMM, bf16x3: K' = 3K ----------------
// stream 0: Ahi x Bhi; stream 1: Alo x Bhi; stream 2: Ahi x Blo
// D[M,N] = A@B^T + bias;  A:[M][K] hi/lo, B:[N][K] hi/lo
// EPI: 0 = bias -> split out; 1 = bias+GELU -> split out; 2 = bias -> fp32 out
// Block 128x128, 8 warps (2m x 4n) of 64x32; kc=64/stage, 3-stage cp.async.
#define ROWB 144   // padded smem row stride in bytes (72 bf16)
#define STG_BYTES 36864   // (128 rows A + 128 rows B) * 144

template<int EPI>
__global__ void __launch_bounds__(256, 1) mma_gemm(
    const bf16* __restrict__ Ahi, const bf16* __restrict__ Alo,
    const bf16* __restrict__ Bhi, const bf16* __restrict__ Blo,
    const float* __restrict__ bias,
    bf16* __restrict__ Chi, bf16* __restrict__ Clo, float* __restrict__ Cf,
    int M, int N, int K)
{
    extern __shared__ char smem[];
    const uint32_t sbase = smem_u32(smem);
    const int t = threadIdx.x, wid = t >> 5, lane = t & 31;
    const int wm = wid >> 2, wn = wid & 3;
    const int g = lane >> 2, tig = lane & 3;
    const int quad = lane >> 3, qr = lane & 7;
    const int bm = blockIdx.y * 128, bn = blockIdx.x * 128;
    const int kc = K >> 6;          // stages per stream (2,4,8)
    const int nst = 3 * kc;         // total pipeline stages

    const int lrow = t >> 3, lc = t & 7;   // loader: 32 rows per pass, chunk 0..7

    auto load_stage = [&](int st) {
        int s = st % 3;
        int grp = st / kc;                       // 0,1,2 stream
        int kk = (st - grp * kc) << 6;           // k offset within stream
        const bf16* As = (grp == 1) ? Alo + kk : Ahi + kk;
        const bf16* Bs = (grp == 2) ? Blo + kk : Bhi + kk;
        uint32_t Ab = sbase + s * STG_BYTES;
        uint32_t Bb = Ab + 128 * ROWB;
        #pragma unroll
        for (int i = 0; i < 4; i++) {
            int row = i * 32 + lrow;
            int grow = bm + row;
            int sz = (grow < M) ? 16 : 0;
            const bf16* src = As + (size_t)((grow < M) ? grow : (M - 1)) * K + lc * 8;
            CP_ASYNC16(Ab + row * ROWB + lc * 16, src, sz);
        }
        #pragma unroll
        for (int i = 0; i < 4; i++) {
            int row = i * 32 + lrow;
            const bf16* src = Bs + (size_t)(bn + row) * K + lc * 8;
            CP_ASYNC16_U(Bb + row * ROWB + lc * 16, src);
        }
    };

    float acc[4][4][4];
    #pragma unroll
    for (int a = 0; a < 4; a++)
        #pragma unroll
        for (int b = 0; b < 4; b++)
            #pragma unroll
            for (int c = 0; c < 4; c++) acc[a][b][c] = 0.f;

    // prologue: 3 commit groups
    #pragma unroll
    for (int s = 0; s < 3; s++) { if (s < nst) load_stage(s); CP_COMMIT(); }

    for (int st = 0; st < nst; ++st) {
        CP_WAIT2();
        __syncthreads();
        int s = st % 3;
        uint32_t Ab = sbase + s * STG_BYTES;
        uint32_t Bb = Ab + 128 * ROWB;
        #pragma unroll
        for (int ks = 0; ks < 4; ks++) {
            int ch = ks * 2 + (quad >> 1);
            uint32_t a[4][4], b[2][4];
            #pragma unroll
            for (int mt = 0; mt < 4; mt++) {
                uint32_t ad = Ab + (uint32_t)(wm * 64 + mt * 16 + (quad & 1) * 8 + qr) * ROWB + ch * 16;
                LDMATRIX_X4(a[mt][0], a[mt][1], a[mt][2], a[mt][3], ad);
            }
            #pragma unroll
            for (int np = 0; np < 2; np++) {
                uint32_t ad = Bb + (uint32_t)(wn * 32 + np * 16 + (quad & 1) * 8 + qr) * ROWB + ch * 16;
                LDMATRIX_X4(b[np][0], b[np][1], b[np][2], b[np][3], ad);
            }
            #pragma unroll
            for (int mt = 0; mt < 4; mt++)
                #pragma unroll
                for (int nt = 0; nt < 4; nt++)
                    MMA16816(acc[mt][nt][0], acc[mt][nt][1], acc[mt][nt][2], acc[mt][nt][3],
                             a[mt][0], a[mt][1], a[mt][2], a[mt][3],
                             b[nt >> 1][nt & 1], b[nt >> 1][2 + (nt & 1)]);
        }
        __syncthreads();
        if (st + 3 < nst) load_stage(st + 3);
        CP_COMMIT();
    }

    // epilogue
    #pragma unroll
    for (int mt = 0; mt < 4; mt++) {
        int r0 = bm + wm * 64 + mt * 16 + g;
        int r1 = r0 + 8;
        #pragma unroll
        for (int nt = 0; nt < 4; nt++) {
            int col = bn + wn * 32 + nt * 8 + tig * 2;
            float bz0 = bias[col], bz1 = bias[col + 1];
            float v0 = acc[mt][nt][0] + bz0, v1 = acc[mt][nt][1] + bz1;
            float v2 = acc[mt][nt][2] + bz0, v3 = acc[mt][nt][3] + bz1;
            if (EPI == 1) {
                v0 = gelu_exact(v0); v1 = gelu_exact(v1);
                v2 = gelu_exact(v2); v3 = gelu_exact(v3);
            }
            if (EPI == 2) {
                if (r0 < M) *(float2*)&Cf[(size_t)r0 * N + col] = make_float2(v0, v1);
                if (r1 < M) *(float2*)&Cf[(size_t)r1 * N + col] = make_float2(v2, v3);
            } else {
                __nv_bfloat162 h, l;
                if (r0 < M) {
                    split2(v0, v1, h, l);
                    *(__nv_bfloat162*)&Chi[(size_t)r0 * N + col] = h;
                    *(__nv_bfloat162*)&Clo[(size_t)r0 * N + col] = l;
                }
                if (r1 < M) {
                    split2(v2, v3, h, l);
                    *(__nv_bfloat162*)&Chi[(size_t)r1 * N + col] = h;
                    *(__nv_bfloat162*)&Clo[(size_t)r1 * N + col] = l;
                }
            }
        }
    }
}

// ---------------- launcher ----------------
extern "C" void kernel_launch(void* const* d_in, const int* in_sizes, int n_in,
                              void* d_out, int out_size) {
    (void)in_sizes; (void)n_in; (void)out_size;
    const float* x          = (const float*)d_in[0];
    const float* batched_x  = (const float*)d_in[1];
    const int*   indices    = (const int*)  d_in[2];
    const float* ln_d_scale = (const float*)d_in[3];
    const float* ln_d_bias  = (const float*)d_in[4];
    const float* W1_d       = (const float*)d_in[5];
    const float* b1_d       = (const float*)d_in[6];
    const float* W2_d       = (const float*)d_in[7];
    const float* b2_d       = (const float*)d_in[8];
    const float* ln_u_scale = (const float*)d_in[9];
    const float* ln_u_bias  = (const float*)d_in[10];
    const float* W1_u       = (const float*)d_in[11];
    const float* b1_u       = (const float*)d_in[12];
    const float* W2_u       = (const float*)d_in[13];
    const float* b2_u       = (const float*)d_in[14];
    float* out = (float*)d_out;

    bf16 *a0h, *a0l, *h1h, *h1l, *ch, *cl, *gh, *gl, *h2h, *h2l;
    bf16 *w1dh, *w1dl, *w2dh, *w2dl, *w1uh, *w1ul, *w2uh, *w2ul;
    cudaGetSymbolAddress((void**)&a0h, g_A0h); cudaGetSymbolAddress((void**)&a0l, g_A0l);
    cudaGetSymbolAddress((void**)&h1h, g_H1h); cudaGetSymbolAddress((void**)&h1l, g_H1l);
    cudaGetSymbolAddress((void**)&ch,  g_Ch);  cudaGetSymbolAddress((void**)&cl,  g_Cl);
    cudaGetSymbolAddress((void**)&gh,  g_Gh);  cudaGetSymbolAddress((void**)&gl,  g_Gl);
    cudaGetSymbolAddress((void**)&h2h, g_H2h); cudaGetSymbolAddress((void**)&h2l, g_H2l);
    cudaGetSymbolAddress((void**)&w1dh, g_w1dh); cudaGetSymbolAddress((void**)&w1dl, g_w1dl);
    cudaGetSymbolAddress((void**)&w2dh, g_w2dh); cudaGetSymbolAddress((void**)&w2dl, g_w2dl);
    cudaGetSymbolAddress((void**)&w1uh, g_w1uh); cudaGetSymbolAddress((void**)&w1ul, g_w1ul);
    cudaGetSymbolAddress((void**)&w2uh, g_w2uh); cudaGetSymbolAddress((void**)&w2ul, g_w2ul);

    const int DYN = 3 * STG_BYTES;   // 110592
    cudaFuncSetAttribute(mma_gemm<0>, cudaFuncAttributeMaxDynamicSharedMemorySize, DYN);
    cudaFuncSetAttribute(mma_gemm<1>, cudaFuncAttributeMaxDynamicSharedMemorySize, DYN);
    cudaFuncSetAttribute(mma_gemm<2>, cudaFuncAttributeMaxDynamicSharedMemorySize, DYN);

    // weight prep
    k_wsplit<<<(H_DIM * E_DIM + 255) / 256, 256>>>(W1_d, w1dh, w1dl, E_DIM, H_DIM);
    k_wsplit<<<(C_DIM * H_DIM + 255) / 256, 256>>>(W2_d, w2dh, w2dl, H_DIM, C_DIM);
    k_wsplit<<<(U_DIM * C_DIM + 255) / 256, 256>>>(W1_u, w1uh, w1ul, C_DIM, U_DIM);
    k_wsplit<<<(E_DIM * U_DIM + 255) / 256, 256>>>(W2_u, w2uh, w2ul, U_DIM, E_DIM);

    // front-end
    const int FB = (ROWS + 7) / 8;
    k_zero_rows<<<FB, 256>>>(indices);
    k_scatter  <<<FB, 256>>>(x, indices);
    k_gather_ln<<<FB, 256>>>(batched_x, indices, ln_d_scale, ln_d_bias);

    // GEMM chain (bf16x3)
    mma_gemm<1><<<dim3(H_DIM / 128, MBLK), 256, DYN>>>(a0h, a0l, w1dh, w1dl, b1_d,
                                                       h1h, h1l, nullptr, ROWS, H_DIM, E_DIM);
    mma_gemm<0><<<dim3(C_DIM / 128, MBLK), 256, DYN>>>(h1h, h1l, w2dh, w2dl, b2_d,
                                                       ch, cl, nullptr, ROWS, C_DIM, H_DIM);
    k_ln128<<<FB, 256>>>(ch, cl, gh, gl, ln_u_scale, ln_u_bias);
    mma_gemm<1><<<dim3(U_DIM / 128, MBLK), 256, DYN>>>(gh, gl, w1uh, w1ul, b1_u,
                                                       h2h, h2l, nullptr, ROWS, U_DIM, C_DIM);
    mma_gemm<2><<<dim3(E_DIM / 128, MBLK), 256, DYN>>>(h2h, h2l, w2uh, w2ul, b2_u,
                                                       nullptr, nullptr, out, ROWS, E_DIM, U_DIM);
}

// round 9
// speedup vs baseline: 2.4514x; 1.1737x over previous
#include <cuda_runtime.h>
#include <cuda_bf16.h>
#include <math.h>
#include <stdint.h>

// ---------------- problem dims (fixed) ----------------
#define T_STEPS   4
#define NODE_NUM  10000
#define NUM_NODES 50000
#define E_DIM     256
#define H_DIM     512
#define C_DIM     128
#define U_DIM     256
#define ROWS      (T_STEPS * NODE_NUM)   // 40000
#define LN_EPS    1e-5f
#define MBLK      ((ROWS + 127) / 128)   // 313

typedef __nv_bfloat16 bf16;

// ---------------- scratch (__device__ globals) ----------------
__device__ float g_S[(size_t)T_STEPS * NUM_NODES * E_DIM];
__device__ bf16 g_A0h[(size_t)ROWS * E_DIM], g_A0l[(size_t)ROWS * E_DIM];
__device__ bf16 g_H1h[(size_t)ROWS * H_DIM], g_H1l[(size_t)ROWS * H_DIM];
__device__ bf16 g_Gh [(size_t)ROWS * C_DIM], g_Gl [(size_t)ROWS * C_DIM];
__device__ bf16 g_H2h[(size_t)ROWS * U_DIM], g_H2l[(size_t)ROWS * U_DIM];
// transposed + split weights, [N][K]
__device__ bf16 g_w1dh[H_DIM * E_DIM], g_w1dl[H_DIM * E_DIM];
__device__ bf16 g_w2dh[C_DIM * H_DIM], g_w2dl[C_DIM * H_DIM];
__device__ bf16 g_w1uh[U_DIM * C_DIM], g_w1ul[U_DIM * C_DIM];
__device__ bf16 g_w2uh[E_DIM * U_DIM], g_w2ul[E_DIM * U_DIM];

// ---------------- helpers ----------------
static __device__ __forceinline__ uint32_t smem_u32(const void* p) {
    uint32_t a;
    asm("{ .reg .u64 t; cvta.to.shared.u64 t, %1; cvt.u32.u64 %0, t; }" : "=r"(a) : "l"(p));
    return a;
}

static __device__ __forceinline__ void split2(float a, float b,
                                              __nv_bfloat162& h, __nv_bfloat162& l) {
    h = __floats2bfloat162_rn(a, b);
    float2 hf = __bfloat1622float2(h);
    l = __floats2bfloat162_rn(a - hf.x, b - hf.y);
}

static __device__ __forceinline__ float gelu_exact(float v) {
    return 0.5f * v * (1.0f + erff(v * 0.70710678118654752f));
}

#define CP_ASYNC16(dst, src, sz) \
    asm volatile("cp.async.cg.shared.global [%0], [%1], 16, %2;" \
                 :: "r"(dst), "l"(src), "r"(sz) : "memory")
#define CP_ASYNC16_U(dst, src) \
    asm volatile("cp.async.cg.shared.global [%0], [%1], 16;" \
                 :: "r"(dst), "l"(src) : "memory")
#define CP_COMMIT() asm volatile("cp.async.commit_group;" ::: "memory")
#define CP_WAIT2()  asm volatile("cp.async.wait_group 2;" ::: "memory")

#define LDMATRIX_X4(r0, r1, r2, r3, addr) \
    asm volatile("ldmatrix.sync.aligned.m8n8.x4.shared.b16 {%0,%1,%2,%3}, [%4];" \
                 : "=r"(r0), "=r"(r1), "=r"(r2), "=r"(r3) : "r"(addr))

#define MMA16816(c0, c1, c2, c3, a0, a1, a2, a3, b0, b1) \
    asm volatile("mma.sync.aligned.m16n8k16.row.col.f32.bf16.bf16.f32 " \
                 "{%0,%1,%2,%3}, {%4,%5,%6,%7}, {%8,%9}, {%0,%1,%2,%3};" \
                 : "+f"(c0), "+f"(c1), "+f"(c2), "+f"(c3) \
                 : "r"(a0), "r"(a1), "r"(a2), "r"(a3), "r"(b0), "r"(b1))

// ---------------- prep: transpose + bf16-split weights ----------------
__global__ void k_wsplit(const float* __restrict__ W, bf16* __restrict__ hi,
                         bf16* __restrict__ lo, int K, int N) {
    int i = blockIdx.x * 256 + threadIdx.x;
    if (i >= N * K) return;
    int n = i / K, k = i % K;
    float v = W[k * N + n];
    bf16 h = __float2bfloat16_rn(v);
    hi[i] = h;
    lo[i] = __float2bfloat16_rn(v - __bfloat162float(h));
}

// ---------------- front-end ----------------
__global__ void k_zero_rows(const int* __restrict__ idx) {
    int r = blockIdx.x * 8 + (threadIdx.x >> 5);
    if (r >= ROWS) return;
    int lane = threadIdx.x & 31;
    int t = r / NODE_NUM;
    int node = idx[r];
    float4* p = (float4*)&g_S[((size_t)t * NUM_NODES + node) * E_DIM];
    float4 z = make_float4(0.f, 0.f, 0.f, 0.f);
    p[lane] = z; p[lane + 32] = z;
}

__global__ void k_scatter(const float* __restrict__ x, const int* __restrict__ idx) {
    int r = blockIdx.x * 8 + (threadIdx.x >> 5);
    if (r >= ROWS) return;
    int lane = threadIdx.x & 31;
    int t = r / NODE_NUM;
    int node = idx[r];
    float* dst = &g_S[((size_t)t * NUM_NODES + node) * E_DIM];
    const float* src = x + (size_t)r * E_DIM;
    #pragma unroll
    for (int j = 0; j < 8; j++)
        atomicAdd(dst + lane + j * 32, src[lane + j * 32]);
}

// gather + broadcast-add + LN(256) -> split bf16 A0
__global__ void k_gather_ln(const float* __restrict__ bx, const int* __restrict__ idx,
                            const float* __restrict__ sc, const float* __restrict__ bi) {
    int r = blockIdx.x * 8 + (threadIdx.x >> 5);
    if (r >= ROWS) return;
    int lane = threadIdx.x & 31;
    int t = r / NODE_NUM;
    int node = idx[r];
    const float* srow = &g_S[((size_t)t * NUM_NODES + node) * E_DIM];
    const float* brow = bx + (size_t)node * E_DIM;
    float4 a0 = *(const float4*)(srow + lane * 4);
    float4 a1 = *(const float4*)(srow + 128 + lane * 4);
    float4 b0 = *(const float4*)(brow + lane * 4);
    float4 b1 = *(const float4*)(brow + 128 + lane * 4);
    float v[8] = { a0.x + b0.x, a0.y + b0.y, a0.z + b0.z, a0.w + b0.w,
                   a1.x + b1.x, a1.y + b1.y, a1.z + b1.z, a1.w + b1.w };
    float s1 = 0.f, s2 = 0.f;
    #pragma unroll
    for (int j = 0; j < 8; j++) { s1 += v[j]; s2 += v[j] * v[j]; }
    #pragma unroll
    for (int o = 16; o > 0; o >>= 1) {
        s1 += __shfl_xor_sync(0xffffffffu, s1, o);
        s2 += __shfl_xor_sync(0xffffffffu, s2, o);
    }
    float mu = s1 * (1.f / 256.f);
    float rs = rsqrtf(s2 * (1.f / 256.f) - mu * mu + LN_EPS);
    #pragma unroll
    for (int half = 0; half < 2; half++) {
        #pragma unroll
        for (int j = 0; j < 2; j++) {
            int c = half * 128 + lane * 4 + j * 2;
            float o0 = (v[half * 4 + j * 2 + 0] - mu) * rs * sc[c]     + bi[c];
            float o1 = (v[half * 4 + j * 2 + 1] - mu) * rs * sc[c + 1] + bi[c + 1];
            __nv_bfloat162 h, l;
            split2(o0, o1, h, l);
            *(__nv_bfloat162*)&g_A0h[(size_t)r * E_DIM + c] = h;
            *(__nv_bfloat162*)&g_A0l[(size_t)r * E_DIM + c] = l;
        }
    }
}

// ---------------- mma.sync bf16 GEMM, bf16x3: K' = 3K ----------------
// EPI: 1 = bias+GELU -> split out; 2 = bias -> fp32 out; 3 = bias+LN -> split out (N==128)
#define ROWB 144            // padded smem row stride in bytes (72 bf16)
#define STG_BYTES 36864     // (128 rows A + 128 rows B) * 144
#define LNPAD 132           // fp32 staging row stride for EPI=3

template<int EPI>
__global__ void __launch_bounds__(256, 2) mma_gemm(
    const bf16* __restrict__ Ahi, const bf16* __restrict__ Alo,
    const bf16* __restrict__ Bhi, const bf16* __restrict__ Blo,
    const float* __restrict__ bias,
    const float* __restrict__ lns, const float* __restrict__ lnb,
    bf16* __restrict__ Chi, bf16* __restrict__ Clo, float* __restrict__ Cf,
    int M, int N, int K)
{
    extern __shared__ char smem[];
    const uint32_t sbase = smem_u32(smem);
    const int t = threadIdx.x, wid = t >> 5, lane = t & 31;
    const int wm = wid >> 2, wn = wid & 3;
    const int g = lane >> 2, tig = lane & 3;
    const int quad = lane >> 3, qr = lane & 7;
    const int bm = blockIdx.y * 128, bn = blockIdx.x * 128;
    const int kc = K >> 6;          // stages per stream
    const int nst = 3 * kc;

    const int lrow = t >> 3, lc = t & 7;

    auto load_stage = [&](int st) {
        int s = st % 3;
        int grp = st / kc;                       // 0,1,2 stream
        int kk = (st - grp * kc) << 6;
        const bf16* As = (grp == 1) ? Alo + kk : Ahi + kk;
        const bf16* Bs = (grp == 2) ? Blo + kk : Bhi + kk;
        uint32_t Ab = sbase + s * STG_BYTES;
        uint32_t Bb = Ab + 128 * ROWB;
        #pragma unroll
        for (int i = 0; i < 4; i++) {
            int row = i * 32 + lrow;
            int grow = bm + row;
            int sz = (grow < M) ? 16 : 0;
            const bf16* src = As + (size_t)((grow < M) ? grow : (M - 1)) * K + lc * 8;
            CP_ASYNC16(Ab + row * ROWB + lc * 16, src, sz);
        }
        #pragma unroll
        for (int i = 0; i < 4; i++) {
            int row = i * 32 + lrow;
            const bf16* src = Bs + (size_t)(bn + row) * K + lc * 8;
            CP_ASYNC16_U(Bb + row * ROWB + lc * 16, src);
        }
    };

    float acc[4][4][4];
    #pragma unroll
    for (int a = 0; a < 4; a++)
        #pragma unroll
        for (int b = 0; b < 4; b++)
            #pragma unroll
            for (int c = 0; c < 4; c++) acc[a][b][c] = 0.f;

    #pragma unroll
    for (int s = 0; s < 3; s++) { if (s < nst) load_stage(s); CP_COMMIT(); }

    for (int st = 0; st < nst; ++st) {
        CP_WAIT2();
        __syncthreads();
        int s = st % 3;
        uint32_t Ab = sbase + s * STG_BYTES;
        uint32_t Bb = Ab + 128 * ROWB;
        #pragma unroll
        for (int ks = 0; ks < 4; ks++) {
            int ch = ks * 2 + (quad >> 1);
            uint32_t a[4][4], b[2][4];
            #pragma unroll
            for (int mt = 0; mt < 4; mt++) {
                uint32_t ad = Ab + (uint32_t)(wm * 64 + mt * 16 + (quad & 1) * 8 + qr) * ROWB + ch * 16;
                LDMATRIX_X4(a[mt][0], a[mt][1], a[mt][2], a[mt][3], ad);
            }
            #pragma unroll
            for (int np = 0; np < 2; np++) {
                uint32_t ad = Bb + (uint32_t)(wn * 32 + np * 16 + (quad & 1) * 8 + qr) * ROWB + ch * 16;
                LDMATRIX_X4(b[np][0], b[np][1], b[np][2], b[np][3], ad);
            }
            #pragma unroll
            for (int mt = 0; mt < 4; mt++)
                #pragma unroll
                for (int nt = 0; nt < 4; nt++)
                    MMA16816(acc[mt][nt][0], acc[mt][nt][1], acc[mt][nt][2], acc[mt][nt][3],
                             a[mt][0], a[mt][1], a[mt][2], a[mt][3],
                             b[nt >> 1][nt & 1], b[nt >> 1][2 + (nt & 1)]);
        }
        __syncthreads();
        if (st + 3 < nst) load_stage(st + 3);
        CP_COMMIT();
    }

    if (EPI == 3) {
        // ---- fused bias + LayerNorm(128) epilogue -> split bf16 out ----
        float* sf = (float*)smem;   // [128][LNPAD] fp32 staging
        __syncthreads();            // smem reuse safe (all loads drained by pipeline end)
        #pragma unroll
        for (int mt = 0; mt < 4; mt++) {
            int lr0 = wm * 64 + mt * 16 + g;
            #pragma unroll
            for (int nt = 0; nt < 4; nt++) {
                int col = wn * 32 + nt * 8 + tig * 2;
                float bz0 = bias[col], bz1 = bias[col + 1];
                sf[lr0 * LNPAD + col]           = acc[mt][nt][0] + bz0;
                sf[lr0 * LNPAD + col + 1]       = acc[mt][nt][1] + bz1;
                sf[(lr0 + 8) * LNPAD + col]     = acc[mt][nt][2] + bz0;
                sf[(lr0 + 8) * LNPAD + col + 1] = acc[mt][nt][3] + bz1;
            }
        }
        __syncthreads();
        // warp-per-row LN: each warp handles 16 rows
        for (int rr = 0; rr < 16; rr++) {
            int lr = wid * 16 + rr;
            int grow = bm + lr;
            float v[4];
            #pragma unroll
            for (int j = 0; j < 4; j++) v[j] = sf[lr * LNPAD + lane * 4 + j];
            float s1 = v[0] + v[1] + v[2] + v[3];
            float s2 = v[0]*v[0] + v[1]*v[1] + v[2]*v[2] + v[3]*v[3];
            #pragma unroll
            for (int o = 16; o > 0; o >>= 1) {
                s1 += __shfl_xor_sync(0xffffffffu, s1, o);
                s2 += __shfl_xor_sync(0xffffffffu, s2, o);
            }
            float mu = s1 * (1.f / 128.f);
            float rs = rsqrtf(s2 * (1.f / 128.f) - mu * mu + LN_EPS);
            if (grow < M) {
                #pragma unroll
                for (int j = 0; j < 2; j++) {
                    int c = lane * 4 + j * 2;
                    float o0 = (v[j * 2 + 0] - mu) * rs * lns[c]     + lnb[c];
                    float o1 = (v[j * 2 + 1] - mu) * rs * lns[c + 1] + lnb[c + 1];
                    __nv_bfloat162 h, l;
                    split2(o0, o1, h, l);
                    *(__nv_bfloat162*)&Chi[(size_t)grow * C_DIM + c] = h;
                    *(__nv_bfloat162*)&Clo[(size_t)grow * C_DIM + c] = l;
                }
            }
        }
    } else {
        #pragma unroll
        for (int mt = 0; mt < 4; mt++) {
            int r0 = bm + wm * 64 + mt * 16 + g;
            int r1 = r0 + 8;
            #pragma unroll
            for (int nt = 0; nt < 4; nt++) {
                int col = bn + wn * 32 + nt * 8 + tig * 2;
                float bz0 = bias[col], bz1 = bias[col + 1];
                float v0 = acc[mt][nt][0] + bz0, v1 = acc[mt][nt][1] + bz1;
                float v2 = acc[mt][nt][2] + bz0, v3 = acc[mt][nt][3] + bz1;
                if (EPI == 1) {
                    v0 = gelu_exact(v0); v1 = gelu_exact(v1);
                    v2 = gelu_exact(v2); v3 = gelu_exact(v3);
                }
                if (EPI == 2) {
                    if (r0 < M) *(float2*)&Cf[(size_t)r0 * N + col] = make_float2(v0, v1);
                    if (r1 < M) *(float2*)&Cf[(size_t)r1 * N + col] = make_float2(v2, v3);
                } else {
                    __nv_bfloat162 h, l;
                    if (r0 < M) {
                        split2(v0, v1, h, l);
                        *(__nv_bfloat162*)&Chi[(size_t)r0 * N + col] = h;
                        *(__nv_bfloat162*)&Clo[(size_t)r0 * N + col] = l;
                    }
                    if (r1 < M) {
                        split2(v2, v3, h, l);
                        *(__nv_bfloat162*)&Chi[(size_t)r1 * N + col] = h;
                        *(__nv_bfloat162*)&Clo[(size_t)r1 * N + col] = l;
                    }
                }
            }
        }
    }
}

// ---------------- launcher ----------------
extern "C" void kernel_launch(void* const* d_in, const int* in_sizes, int n_in,
                              void* d_out, int out_size) {
    (void)in_sizes; (void)n_in; (void)out_size;
    const float* x          = (const float*)d_in[0];
    const float* batched_x  = (const float*)d_in[1];
    const int*   indices    = (const int*)  d_in[2];
    const float* ln_d_scale = (const float*)d_in[3];
    const float* ln_d_bias  = (const float*)d_in[4];
    const float* W1_d       = (const float*)d_in[5];
    const float* b1_d       = (const float*)d_in[6];
    const float* W2_d       = (const float*)d_in[7];
    const float* b2_d       = (const float*)d_in[8];
    const float* ln_u_scale = (const float*)d_in[9];
    const float* ln_u_bias  = (const float*)d_in[10];
    const float* W1_u       = (const float*)d_in[11];
    const float* b1_u       = (const float*)d_in[12];
    const float* W2_u       = (const float*)d_in[13];
    const float* b2_u       = (const float*)d_in[14];
    float* out = (float*)d_out;

    bf16 *a0h, *a0l, *h1h, *h1l, *gh, *gl, *h2h, *h2l;
    bf16 *w1dh, *w1dl, *w2dh, *w2dl, *w1uh, *w1ul, *w2uh, *w2ul;
    cudaGetSymbolAddress((void**)&a0h, g_A0h); cudaGetSymbolAddress((void**)&a0l, g_A0l);
    cudaGetSymbolAddress((void**)&h1h, g_H1h); cudaGetSymbolAddress((void**)&h1l, g_H1l);
    cudaGetSymbolAddress((void**)&gh,  g_Gh);  cudaGetSymbolAddress((void**)&gl,  g_Gl);
    cudaGetSymbolAddress((void**)&h2h, g_H2h); cudaGetSymbolAddress((void**)&h2l, g_H2l);
    cudaGetSymbolAddress((void**)&w1dh, g_w1dh); cudaGetSymbolAddress((void**)&w1dl, g_w1dl);
    cudaGetSymbolAddress((void**)&w2dh, g_w2dh); cudaGetSymbolAddress((void**)&w2dl, g_w2dl);
    cudaGetSymbolAddress((void**)&w1uh, g_w1uh); cudaGetSymbolAddress((void**)&w1ul, g_w1ul);
    cudaGetSymbolAddress((void**)&w2uh, g_w2uh); cudaGetSymbolAddress((void**)&w2ul, g_w2ul);

    const int DYN = 3 * STG_BYTES;   // 110592
    cudaFuncSetAttribute(mma_gemm<1>, cudaFuncAttributeMaxDynamicSharedMemorySize, DYN);
    cudaFuncSetAttribute(mma_gemm<2>, cudaFuncAttributeMaxDynamicSharedMemorySize, DYN);
    cudaFuncSetAttribute(mma_gemm<3>, cudaFuncAttributeMaxDynamicSharedMemorySize, DYN);

    // weight prep
    k_wsplit<<<(H_DIM * E_DIM + 255) / 256, 256>>>(W1_d, w1dh, w1dl, E_DIM, H_DIM);
    k_wsplit<<<(C_DIM * H_DIM + 255) / 256, 256>>>(W2_d, w2dh, w2dl, H_DIM, C_DIM);
    k_wsplit<<<(U_DIM * C_DIM + 255) / 256, 256>>>(W1_u, w1uh, w1ul, C_DIM, U_DIM);
    k_wsplit<<<(E_DIM * U_DIM + 255) / 256, 256>>>(W2_u, w2uh, w2ul, U_DIM, E_DIM);

    // front-end
    const int FB = (ROWS + 7) / 8;
    k_zero_rows<<<FB, 256>>>(indices);
    k_scatter  <<<FB, 256>>>(x, indices);
    k_gather_ln<<<FB, 256>>>(batched_x, indices, ln_d_scale, ln_d_bias);

    // GEMM chain (bf16x3)
    mma_gemm<1><<<dim3(H_DIM / 128, MBLK), 256, DYN>>>(a0h, a0l, w1dh, w1dl, b1_d,
                                                       nullptr, nullptr,
                                                       h1h, h1l, nullptr, ROWS, H_DIM, E_DIM);
    mma_gemm<3><<<dim3(1, MBLK), 256, DYN>>>(h1h, h1l, w2dh, w2dl, b2_d,
                                             ln_u_scale, ln_u_bias,
                                             gh, gl, nullptr, ROWS, C_DIM, H_DIM);
    mma_gemm<1><<<dim3(U_DIM / 128, MBLK), 256, DYN>>>(gh, gl, w1uh, w1ul, b1_u,
                                                       nullptr, nullptr,
                                                       h2h, h2l, nullptr, ROWS, U_DIM, C_DIM);
    mma_gemm<2><<<dim3(E_DIM / 128, MBLK), 256, DYN>>>(h2h, h2l, w2uh, w2ul, b2_u,
                                                       nullptr, nullptr,
                                                       nullptr, nullptr, out, ROWS, E_DIM, U_DIM);
}

// round 10
// speedup vs baseline: 2.4656x; 1.0058x over previous
#include <cuda_runtime.h>
#include <cuda_bf16.h>
#include <math.h>
#include <stdint.h>

// ---------------- problem dims (fixed) ----------------
#define T_STEPS   4
#define NODE_NUM  10000
#define NUM_NODES 50000
#define E_DIM     256
#define H_DIM     512
#define C_DIM     128
#define U_DIM     256
#define ROWS      (T_STEPS * NODE_NUM)   // 40000
#define LN_EPS    1e-5f
#define MBLK      ((ROWS + 127) / 128)   // 313

typedef __nv_bfloat16 bf16;

// ---------------- scratch (__device__ globals) ----------------
__device__ float g_S[(size_t)T_STEPS * NUM_NODES * E_DIM];
__device__ int   g_cnt[T_STEPS * NUM_NODES];
__device__ int   g_tick[ROWS];
__device__ bf16 g_A0h[(size_t)ROWS * E_DIM], g_A0l[(size_t)ROWS * E_DIM];
__device__ bf16 g_H1h[(size_t)ROWS * H_DIM], g_H1l[(size_t)ROWS * H_DIM];
__device__ bf16 g_Gh [(size_t)ROWS * C_DIM], g_Gl [(size_t)ROWS * C_DIM];
__device__ bf16 g_H2h[(size_t)ROWS * U_DIM], g_H2l[(size_t)ROWS * U_DIM];
// transposed + split weights, [N][K]
__device__ bf16 g_w1dh[H_DIM * E_DIM], g_w1dl[H_DIM * E_DIM];
__device__ bf16 g_w2dh[C_DIM * H_DIM], g_w2dl[C_DIM * H_DIM];
__device__ bf16 g_w1uh[U_DIM * C_DIM], g_w1ul[U_DIM * C_DIM];
__device__ bf16 g_w2uh[E_DIM * U_DIM], g_w2ul[E_DIM * U_DIM];

// ---------------- helpers ----------------
static __device__ __forceinline__ uint32_t smem_u32(const void* p) {
    uint32_t a;
    asm("{ .reg .u64 t; cvta.to.shared.u64 t, %1; cvt.u32.u64 %0, t; }" : "=r"(a) : "l"(p));
    return a;
}

static __device__ __forceinline__ void split2(float a, float b,
                                              __nv_bfloat162& h, __nv_bfloat162& l) {
    h = __floats2bfloat162_rn(a, b);
    float2 hf = __bfloat1622float2(h);
    l = __floats2bfloat162_rn(a - hf.x, b - hf.y);
}

static __device__ __forceinline__ float gelu_exact(float v) {
    return 0.5f * v * (1.0f + erff(v * 0.70710678118654752f));
}

#define CP_ASYNC16(dst, src, sz) \
    asm volatile("cp.async.cg.shared.global [%0], [%1], 16, %2;" \
                 :: "r"(dst), "l"(src), "r"(sz) : "memory")
#define CP_ASYNC16_U(dst, src) \
    asm volatile("cp.async.cg.shared.global [%0], [%1], 16;" \
                 :: "r"(dst), "l"(src) : "memory")
#define CP_COMMIT() asm volatile("cp.async.commit_group;" ::: "memory")
#define CP_WAIT1()  asm volatile("cp.async.wait_group 1;" ::: "memory")

#define LDMATRIX_X4(r0, r1, r2, r3, addr) \
    asm volatile("ldmatrix.sync.aligned.m8n8.x4.shared.b16 {%0,%1,%2,%3}, [%4];" \
                 : "=r"(r0), "=r"(r1), "=r"(r2), "=r"(r3) : "r"(addr))

#define MMA16816(c0, c1, c2, c3, a0, a1, a2, a3, b0, b1) \
    asm volatile("mma.sync.aligned.m16n8k16.row.col.f32.bf16.bf16.f32 " \
                 "{%0,%1,%2,%3}, {%4,%5,%6,%7}, {%8,%9}, {%0,%1,%2,%3};" \
                 : "+f"(c0), "+f"(c1), "+f"(c2), "+f"(c3) \
                 : "r"(a0), "r"(a1), "r"(a2), "r"(a3), "r"(b0), "r"(b1))

// ---------------- prep: coalesced transpose + bf16-split weights ----------------
// W: [K][N] fp32 -> hi/lo: [N][K] bf16.  grid (N/32, K/32), block (32, 8)
__global__ void k_wsplit(const float* __restrict__ W, bf16* __restrict__ hi,
                         bf16* __restrict__ lo, int K, int N) {
    __shared__ float tile[32][33];
    int nb = blockIdx.x * 32, kb = blockIdx.y * 32;
    int tx = threadIdx.x, ty = threadIdx.y;
    #pragma unroll
    for (int i = 0; i < 32; i += 8)
        tile[ty + i][tx] = W[(size_t)(kb + ty + i) * N + nb + tx];
    __syncthreads();
    #pragma unroll
    for (int i = 0; i < 32; i += 8) {
        int n = nb + ty + i, k = kb + tx;
        float v = tile[tx][ty + i];
        bf16 h = __float2bfloat16_rn(v);
        hi[(size_t)n * K + k] = h;
        lo[(size_t)n * K + k] = __float2bfloat16_rn(v - __bfloat162float(h));
    }
}

// ---------------- front-end (duplicate-aware) ----------------
__global__ void k_clr() {
    int i = blockIdx.x * 256 + threadIdx.x;
    if (i < T_STEPS * NUM_NODES) g_cnt[i] = 0;
}

__global__ void k_count(const int* __restrict__ idx) {
    int r = blockIdx.x * 256 + threadIdx.x;
    if (r >= ROWS) return;
    int t = r / NODE_NUM;
    g_tick[r] = atomicAdd(&g_cnt[t * NUM_NODES + idx[r]], 1);
}

// zero g_S rows only for duplicated (t,node); one designated row per node
__global__ void k_zero_dup(const int* __restrict__ idx) {
    int r = blockIdx.x * 8 + (threadIdx.x >> 5);
    if (r >= ROWS) return;
    int t = r / NODE_NUM;
    int node = idx[r];
    if (g_cnt[t * NUM_NODES + node] < 2 || g_tick[r] != 0) return;
    int lane = threadIdx.x & 31;
    float4* p = (float4*)&g_S[((size_t)t * NUM_NODES + node) * E_DIM];
    float4 z = make_float4(0.f, 0.f, 0.f, 0.f);
    p[lane] = z; p[lane + 32] = z;
}

// scatter-add only duplicated rows
__global__ void k_scat_dup(const float* __restrict__ x, const int* __restrict__ idx) {
    int r = blockIdx.x * 8 + (threadIdx.x >> 5);
    if (r >= ROWS) return;
    int t = r / NODE_NUM;
    int node = idx[r];
    if (g_cnt[t * NUM_NODES + node] < 2) return;
    int lane = threadIdx.x & 31;
    float* dst = &g_S[((size_t)t * NUM_NODES + node) * E_DIM];
    const float* src = x + (size_t)r * E_DIM;
    #pragma unroll
    for (int j = 0; j < 8; j++)
        atomicAdd(dst + lane + j * 32, src[lane + j * 32]);
}

// gather + broadcast-add + LN(256) -> split bf16 A0
__global__ void k_gather_ln(const float* __restrict__ x, const float* __restrict__ bx,
                            const int* __restrict__ idx,
                            const float* __restrict__ sc, const float* __restrict__ bi) {
    int r = blockIdx.x * 8 + (threadIdx.x >> 5);
    if (r >= ROWS) return;
    int lane = threadIdx.x & 31;
    int t = r / NODE_NUM;
    int node = idx[r];
    const float* srow = (g_cnt[t * NUM_NODES + node] < 2)
                      ? (x + (size_t)r * E_DIM)
                      : &g_S[((size_t)t * NUM_NODES + node) * E_DIM];
    const float* brow = bx + (size_t)node * E_DIM;
    float4 a0 = *(const float4*)(srow + lane * 4);
    float4 a1 = *(const float4*)(srow + 128 + lane * 4);
    float4 b0 = *(const float4*)(brow + lane * 4);
    float4 b1 = *(const float4*)(brow + 128 + lane * 4);
    float v[8] = { a0.x + b0.x, a0.y + b0.y, a0.z + b0.z, a0.w + b0.w,
                   a1.x + b1.x, a1.y + b1.y, a1.z + b1.z, a1.w + b1.w };
    float s1 = 0.f, s2 = 0.f;
    #pragma unroll
    for (int j = 0; j < 8; j++) { s1 += v[j]; s2 += v[j] * v[j]; }
    #pragma unroll
    for (int o = 16; o > 0; o >>= 1) {
        s1 += __shfl_xor_sync(0xffffffffu, s1, o);
        s2 += __shfl_xor_sync(0xffffffffu, s2, o);
    }
    float mu = s1 * (1.f / 256.f);
    float rs = rsqrtf(s2 * (1.f / 256.f) - mu * mu + LN_EPS);
    #pragma unroll
    for (int half = 0; half < 2; half++) {
        #pragma unroll
        for (int j = 0; j < 2; j++) {
            int c = half * 128 + lane * 4 + j * 2;
            float o0 = (v[half * 4 + j * 2 + 0] - mu) * rs * sc[c]     + bi[c];
            float o1 = (v[half * 4 + j * 2 + 1] - mu) * rs * sc[c + 1] + bi[c + 1];
            __nv_bfloat162 h, l;
            split2(o0, o1, h, l);
            *(__nv_bfloat162*)&g_A0h[(size_t)r * E_DIM + c] = h;
            *(__nv_bfloat162*)&g_A0l[(size_t)r * E_DIM + c] = l;
        }
    }
}

// ---------------- mma.sync bf16 GEMM, bf16x3: K' = 3K ----------------
// EPI: 1 = bias+GELU -> split out; 2 = bias -> fp32 out; 3 = bias+LN -> split out (N==128)
// Pipeline: 3 buffers, prefetch depth 2, wait_group 1, ONE __syncthreads per stage.
#define ROWB 144            // padded smem row stride in bytes (72 bf16)
#define STG_BYTES 36864     // (128 rows A + 128 rows B) * 144
#define LNPAD 132           // fp32 staging row stride for EPI=3

template<int EPI>
__global__ void __launch_bounds__(256, 2) mma_gemm(
    const bf16* __restrict__ Ahi, const bf16* __restrict__ Alo,
    const bf16* __restrict__ Bhi, const bf16* __restrict__ Blo,
    const float* __restrict__ bias,
    const float* __restrict__ lns, const float* __restrict__ lnb,
    bf16* __restrict__ Chi, bf16* __restrict__ Clo, float* __restrict__ Cf,
    int M, int N, int K)
{
    extern __shared__ char smem[];
    const uint32_t sbase = smem_u32(smem);
    const int t = threadIdx.x, wid = t >> 5, lane = t & 31;
    const int wm = wid >> 2, wn = wid & 3;
    const int g = lane >> 2, tig = lane & 3;
    const int quad = lane >> 3, qr = lane & 7;
    const int bm = blockIdx.y * 128, bn = blockIdx.x * 128;
    const int kc = K >> 6;          // stages per stream
    const int nst = 3 * kc;

    const int lrow = t >> 3, lc = t & 7;

    auto load_stage = [&](int st) {
        int s = st % 3;
        int grp = st / kc;                       // 0,1,2 stream
        int kk = (st - grp * kc) << 6;
        const bf16* As = (grp == 1) ? Alo + kk : Ahi + kk;
        const bf16* Bs = (grp == 2) ? Blo + kk : Bhi + kk;
        uint32_t Ab = sbase + s * STG_BYTES;
        uint32_t Bb = Ab + 128 * ROWB;
        #pragma unroll
        for (int i = 0; i < 4; i++) {
            int row = i * 32 + lrow;
            int grow = bm + row;
            int sz = (grow < M) ? 16 : 0;
            const bf16* src = As + (size_t)((grow < M) ? grow : (M - 1)) * K + lc * 8;
            CP_ASYNC16(Ab + row * ROWB + lc * 16, src, sz);
        }
        #pragma unroll
        for (int i = 0; i < 4; i++) {
            int row = i * 32 + lrow;
            const bf16* src = Bs + (size_t)(bn + row) * K + lc * 8;
            CP_ASYNC16_U(Bb + row * ROWB + lc * 16, src);
        }
    };

    float acc[4][4][4];
    #pragma unroll
    for (int a = 0; a < 4; a++)
        #pragma unroll
        for (int b = 0; b < 4; b++)
            #pragma unroll
            for (int c = 0; c < 4; c++) acc[a][b][c] = 0.f;

    // prologue: depth-2 prefetch
    load_stage(0); CP_COMMIT();
    load_stage(1); CP_COMMIT();

    for (int st = 0; st < nst; ++st) {
        CP_WAIT1();            // stage st data arrived
        __syncthreads();       // everyone past stage st-1 reads; buffer (st+2)%3 free
        if (st + 2 < nst) load_stage(st + 2);
        CP_COMMIT();
        int s = st % 3;
        uint32_t Ab = sbase + s * STG_BYTES;
        uint32_t Bb = Ab + 128 * ROWB;
        #pragma unroll
        for (int ks = 0; ks < 4; ks++) {
            int ch = ks * 2 + (quad >> 1);
            uint32_t a[4][4], b[2][4];
            #pragma unroll
            for (int mt = 0; mt < 4; mt++) {
                uint32_t ad = Ab + (uint32_t)(wm * 64 + mt * 16 + (quad & 1) * 8 + qr) * ROWB + ch * 16;
                LDMATRIX_X4(a[mt][0], a[mt][1], a[mt][2], a[mt][3], ad);
            }
            #pragma unroll
            for (int np = 0; np < 2; np++) {
                uint32_t ad = Bb + (uint32_t)(wn * 32 + np * 16 + (quad & 1) * 8 + qr) * ROWB + ch * 16;
                LDMATRIX_X4(b[np][0], b[np][1], b[np][2], b[np][3], ad);
            }
            #pragma unroll
            for (int mt = 0; mt < 4; mt++)
                #pragma unroll
                for (int nt = 0; nt < 4; nt++)
                    MMA16816(acc[mt][nt][0], acc[mt][nt][1], acc[mt][nt][2], acc[mt][nt][3],
                             a[mt][0], a[mt][1], a[mt][2], a[mt][3],
                             b[nt >> 1][nt & 1], b[nt >> 1][2 + (nt & 1)]);
        }
    }

    if (EPI == 3) {
        // ---- fused bias + LayerNorm(128) epilogue -> split bf16 out ----
        float* sf = (float*)smem;   // [128][LNPAD] fp32 staging
        __syncthreads();
        #pragma unroll
        for (int mt = 0; mt < 4; mt++) {
            int lr0 = wm * 64 + mt * 16 + g;
            #pragma unroll
            for (int nt = 0; nt < 4; nt++) {
                int col = wn * 32 + nt * 8 + tig * 2;
                float bz0 = bias[col], bz1 = bias[col + 1];
                sf[lr0 * LNPAD + col]           = acc[mt][nt][0] + bz0;
                sf[lr0 * LNPAD + col + 1]       = acc[mt][nt][1] + bz1;
                sf[(lr0 + 8) * LNPAD + col]     = acc[mt][nt][2] + bz0;
                sf[(lr0 + 8) * LNPAD + col + 1] = acc[mt][nt][3] + bz1;
            }
        }
        __syncthreads();
        for (int rr = 0; rr < 16; rr++) {
            int lr = wid * 16 + rr;
            int grow = bm + lr;
            float v[4];
            #pragma unroll
            for (int j = 0; j < 4; j++) v[j] = sf[lr * LNPAD + lane * 4 + j];
            float s1 = v[0] + v[1] + v[2] + v[3];
            float s2 = v[0]*v[0] + v[1]*v[1] + v[2]*v[2] + v[3]*v[3];
            #pragma unroll
            for (int o = 16; o > 0; o >>= 1) {
                s1 += __shfl_xor_sync(0xffffffffu, s1, o);
                s2 += __shfl_xor_sync(0xffffffffu, s2, o);
            }
            float mu = s1 * (1.f / 128.f);
            float rs = rsqrtf(s2 * (1.f / 128.f) - mu * mu + LN_EPS);
            if (grow < M) {
                #pragma unroll
                for (int j = 0; j < 2; j++) {
                    int c = lane * 4 + j * 2;
                    float o0 = (v[j * 2 + 0] - mu) * rs * lns[c]     + lnb[c];
                    float o1 = (v[j * 2 + 1] - mu) * rs * lns[c + 1] + lnb[c + 1];
                    __nv_bfloat162 h, l;
                    split2(o0, o1, h, l);
                    *(__nv_bfloat162*)&Chi[(size_t)grow * C_DIM + c] = h;
                    *(__nv_bfloat162*)&Clo[(size_t)grow * C_DIM + c] = l;
                }
            }
        }
    } else {
        #pragma unroll
        for (int mt = 0; mt < 4; mt++) {
            int r0 = bm + wm * 64 + mt * 16 + g;
            int r1 = r0 + 8;
            #pragma unroll
            for (int nt = 0; nt < 4; nt++) {
                int col = bn + wn * 32 + nt * 8 + tig * 2;
                float bz0 = bias[col], bz1 = bias[col + 1];
                float v0 = acc[mt][nt][0] + bz0, v1 = acc[mt][nt][1] + bz1;
                float v2 = acc[mt][nt][2] + bz0, v3 = acc[mt][nt][3] + bz1;
                if (EPI == 1) {
                    v0 = gelu_exact(v0); v1 = gelu_exact(v1);
                    v2 = gelu_exact(v2); v3 = gelu_exact(v3);
                }
                if (EPI == 2) {
                    if (r0 < M) *(float2*)&Cf[(size_t)r0 * N + col] = make_float2(v0, v1);
                    if (r1 < M) *(float2*)&Cf[(size_t)r1 * N + col] = make_float2(v2, v3);
                } else {
                    __nv_bfloat162 h, l;
                    if (r0 < M) {
                        split2(v0, v1, h, l);
                        *(__nv_bfloat162*)&Chi[(size_t)r0 * N + col] = h;
                        *(__nv_bfloat162*)&Clo[(size_t)r0 * N + col] = l;
                    }
                    if (r1 < M) {
                        split2(v2, v3, h, l);
                        *(__nv_bfloat162*)&Chi[(size_t)r1 * N + col] = h;
                        *(__nv_bfloat162*)&Clo[(size_t)r1 * N + col] = l;
                    }
                }
            }
        }
    }
}

// ---------------- launcher ----------------
extern "C" void kernel_launch(void* const* d_in, const int* in_sizes, int n_in,
                              void* d_out, int out_size) {
    (void)in_sizes; (void)n_in; (void)out_size;
    const float* x          = (const float*)d_in[0];
    const float* batched_x  = (const float*)d_in[1];
    const int*   indices    = (const int*)  d_in[2];
    const float* ln_d_scale = (const float*)d_in[3];
    const float* ln_d_bias  = (const float*)d_in[4];
    const float* W1_d       = (const float*)d_in[5];
    const float* b1_d       = (const float*)d_in[6];
    const float* W2_d       = (const float*)d_in[7];
    const float* b2_d       = (const float*)d_in[8];
    const float* ln_u_scale = (const float*)d_in[9];
    const float* ln_u_bias  = (const float*)d_in[10];
    const float* W1_u       = (const float*)d_in[11];
    const float* b1_u       = (const float*)d_in[12];
    const float* W2_u       = (const float*)d_in[13];
    const float* b2_u       = (const float*)d_in[14];
    float* out = (float*)d_out;

    bf16 *a0h, *a0l, *h1h, *h1l, *gh, *gl, *h2h, *h2l;
    bf16 *w1dh, *w1dl, *w2dh, *w2dl, *w1uh, *w1ul, *w2uh, *w2ul;
    cudaGetSymbolAddress((void**)&a0h, g_A0h); cudaGetSymbolAddress((void**)&a0l, g_A0l);
    cudaGetSymbolAddress((void**)&h1h, g_H1h); cudaGetSymbolAddress((void**)&h1l, g_H1l);
    cudaGetSymbolAddress((void**)&gh,  g_Gh);  cudaGetSymbolAddress((void**)&gl,  g_Gl);
    cudaGetSymbolAddress((void**)&h2h, g_H2h); cudaGetSymbolAddress((void**)&h2l, g_H2l);
    cudaGetSymbolAddress((void**)&w1dh, g_w1dh); cudaGetSymbolAddress((void**)&w1dl, g_w1dl);
    cudaGetSymbolAddress((void**)&w2dh, g_w2dh); cudaGetSymbolAddress((void**)&w2dl, g_w2dl);
    cudaGetSymbolAddress((void**)&w1uh, g_w1uh); cudaGetSymbolAddress((void**)&w1ul, g_w1ul);
    cudaGetSymbolAddress((void**)&w2uh, g_w2uh); cudaGetSymbolAddress((void**)&w2ul, g_w2ul);

    const int DYN = 3 * STG_BYTES;   // 110592
    cudaFuncSetAttribute(mma_gemm<1>, cudaFuncAttributeMaxDynamicSharedMemorySize, DYN);
    cudaFuncSetAttribute(mma_gemm<2>, cudaFuncAttributeMaxDynamicSharedMemorySize, DYN);
    cudaFuncSetAttribute(mma_gemm<3>, cudaFuncAttributeMaxDynamicSharedMemorySize, DYN);

    // weight prep (coalesced transpose + split)
    dim3 tb(32, 8);
    k_wsplit<<<dim3(H_DIM / 32, E_DIM / 32), tb>>>(W1_d, w1dh, w1dl, E_DIM, H_DIM);
    k_wsplit<<<dim3(C_DIM / 32, H_DIM / 32), tb>>>(W2_d, w2dh, w2dl, H_DIM, C_DIM);
    k_wsplit<<<dim3(U_DIM / 32, C_DIM / 32), tb>>>(W1_u, w1uh, w1ul, C_DIM, U_DIM);
    k_wsplit<<<dim3(E_DIM / 32, U_DIM / 32), tb>>>(W2_u, w2uh, w2ul, U_DIM, E_DIM);

    // front-end (duplicate-aware)
    const int FB = (ROWS + 7) / 8;
    k_clr     <<<(T_STEPS * NUM_NODES + 255) / 256, 256>>>();
    k_count   <<<(ROWS + 255) / 256, 256>>>(indices);
    k_zero_dup<<<FB, 256>>>(indices);
    k_scat_dup<<<FB, 256>>>(x, indices);
    k_gather_ln<<<FB, 256>>>(x, batched_x, indices, ln_d_scale, ln_d_bias);

    // GEMM chain (bf16x3)
    mma_gemm<1><<<dim3(H_DIM / 128, MBLK), 256, DYN>>>(a0h, a0l, w1dh, w1dl, b1_d,
                                                       nullptr, nullptr,
                                                       h1h, h1l, nullptr, ROWS, H_DIM, E_DIM);
    mma_gemm<3><<<dim3(1, MBLK), 256, DYN>>>(h1h, h1l, w2dh, w2dl, b2_d,
                                             ln_u_scale, ln_u_bias,
                                             gh, gl, nullptr, ROWS, C_DIM, H_DIM);
    mma_gemm<1><<<dim3(U_DIM / 128, MBLK), 256, DYN>>>(gh, gl, w1uh, w1ul, b1_u,
                                                       nullptr, nullptr,
                                                       h2h, h2l, nullptr, ROWS, U_DIM, C_DIM);
    mma_gemm<2><<<dim3(E_DIM / 128, MBLK), 256, DYN>>>(h2h, h2l, w2uh, w2ul, b2_u,
                                                       nullptr, nullptr,
                                                       nullptr, nullptr, out, ROWS, E_DIM, U_DIM);
}

// round 11
// speedup vs baseline: 3.4303x; 1.3912x over previous
#include <cuda_runtime.h>
#include <cuda_fp16.h>
#include <math.h>
#include <stdint.h>

// ---------------- problem dims (fixed) ----------------
#define T_STEPS   4
#define NODE_NUM  10000
#define NUM_NODES 50000
#define E_DIM     256
#define H_DIM     512
#define C_DIM     128
#define U_DIM     256
#define ROWS      (T_STEPS * NODE_NUM)   // 40000
#define LN_EPS    1e-5f
#define MBLK      ((ROWS + 127) / 128)   // 313

// ---------------- scratch (__device__ globals) ----------------
__device__ float g_S[(size_t)T_STEPS * NUM_NODES * E_DIM];
__device__ int   g_cnt[T_STEPS * NUM_NODES];
__device__ int   g_tick[ROWS];
// fp16 activations (single array each)
__device__ __half g_A0[(size_t)ROWS * E_DIM];
__device__ __half g_H1[(size_t)ROWS * H_DIM];
__device__ __half g_G [(size_t)ROWS * C_DIM];
__device__ __half g_H2[(size_t)ROWS * U_DIM];
// transposed + split fp16 weights, [N][K]
__device__ __half g_w1dh[H_DIM * E_DIM], g_w1dl[H_DIM * E_DIM];
__device__ __half g_w2dh[C_DIM * H_DIM], g_w2dl[C_DIM * H_DIM];
__device__ __half g_w1uh[U_DIM * C_DIM], g_w1ul[U_DIM * C_DIM];
__device__ __half g_w2uh[E_DIM * U_DIM], g_w2ul[E_DIM * U_DIM];

// ---------------- helpers ----------------
static __device__ __forceinline__ uint32_t smem_u32(const void* p) {
    uint32_t a;
    asm("{ .reg .u64 t; cvta.to.shared.u64 t, %1; cvt.u32.u64 %0, t; }" : "=r"(a) : "l"(p));
    return a;
}

static __device__ __forceinline__ float gelu_exact(float v) {
    return 0.5f * v * (1.0f + erff(v * 0.70710678118654752f));
}

#define CP_ASYNC16(dst, src, sz) \
    asm volatile("cp.async.cg.shared.global [%0], [%1], 16, %2;" \
                 :: "r"(dst), "l"(src), "r"(sz) : "memory")
#define CP_ASYNC16_U(dst, src) \
    asm volatile("cp.async.cg.shared.global [%0], [%1], 16;" \
                 :: "r"(dst), "l"(src) : "memory")
#define CP_COMMIT() asm volatile("cp.async.commit_group;" ::: "memory")
#define CP_WAIT1()  asm volatile("cp.async.wait_group 1;" ::: "memory")

#define LDMATRIX_X4(r0, r1, r2, r3, addr) \
    asm volatile("ldmatrix.sync.aligned.m8n8.x4.shared.b16 {%0,%1,%2,%3}, [%4];" \
                 : "=r"(r0), "=r"(r1), "=r"(r2), "=r"(r3) : "r"(addr))

#define MMA16816(c0, c1, c2, c3, a0, a1, a2, a3, b0, b1) \
    asm volatile("mma.sync.aligned.m16n8k16.row.col.f32.f16.f16.f32 " \
                 "{%0,%1,%2,%3}, {%4,%5,%6,%7}, {%8,%9}, {%0,%1,%2,%3};" \
                 : "+f"(c0), "+f"(c1), "+f"(c2), "+f"(c3) \
                 : "r"(a0), "r"(a1), "r"(a2), "r"(a3), "r"(b0), "r"(b1))

// ---------------- prep: coalesced transpose + fp16-split weights ----------------
// W: [K][N] fp32 -> hi/lo: [N][K] fp16.  grid (N/32, K/32), block (32, 8)
__global__ void k_wsplit(const float* __restrict__ W, __half* __restrict__ hi,
                         __half* __restrict__ lo, int K, int N) {
    __shared__ float tile[32][33];
    int nb = blockIdx.x * 32, kb = blockIdx.y * 32;
    int tx = threadIdx.x, ty = threadIdx.y;
    #pragma unroll
    for (int i = 0; i < 32; i += 8)
        tile[ty + i][tx] = W[(size_t)(kb + ty + i) * N + nb + tx];
    __syncthreads();
    #pragma unroll
    for (int i = 0; i < 32; i += 8) {
        int n = nb + ty + i, k = kb + tx;
        float v = tile[tx][ty + i];
        __half h = __float2half_rn(v);
        hi[(size_t)n * K + k] = h;
        lo[(size_t)n * K + k] = __float2half_rn(v - __half2float(h));
    }
}

// ---------------- front-end (duplicate-aware) ----------------
__global__ void k_clr() {
    int i = blockIdx.x * 256 + threadIdx.x;
    if (i < T_STEPS * NUM_NODES) g_cnt[i] = 0;
}

__global__ void k_count(const int* __restrict__ idx) {
    int r = blockIdx.x * 256 + threadIdx.x;
    if (r >= ROWS) return;
    int t = r / NODE_NUM;
    g_tick[r] = atomicAdd(&g_cnt[t * NUM_NODES + idx[r]], 1);
}

__global__ void k_zero_dup(const int* __restrict__ idx) {
    int r = blockIdx.x * 8 + (threadIdx.x >> 5);
    if (r >= ROWS) return;
    int t = r / NODE_NUM;
    int node = idx[r];
    if (g_cnt[t * NUM_NODES + node] < 2 || g_tick[r] != 0) return;
    int lane = threadIdx.x & 31;
    float4* p = (float4*)&g_S[((size_t)t * NUM_NODES + node) * E_DIM];
    float4 z = make_float4(0.f, 0.f, 0.f, 0.f);
    p[lane] = z; p[lane + 32] = z;
}

__global__ void k_scat_dup(const float* __restrict__ x, const int* __restrict__ idx) {
    int r = blockIdx.x * 8 + (threadIdx.x >> 5);
    if (r >= ROWS) return;
    int t = r / NODE_NUM;
    int node = idx[r];
    if (g_cnt[t * NUM_NODES + node] < 2) return;
    int lane = threadIdx.x & 31;
    float* dst = &g_S[((size_t)t * NUM_NODES + node) * E_DIM];
    const float* src = x + (size_t)r * E_DIM;
    #pragma unroll
    for (int j = 0; j < 8; j++)
        atomicAdd(dst + lane + j * 32, src[lane + j * 32]);
}

// gather + broadcast-add + LN(256) -> fp16 A0
__global__ void k_gather_ln(const float* __restrict__ x, const float* __restrict__ bx,
                            const int* __restrict__ idx,
                            const float* __restrict__ sc, const float* __restrict__ bi) {
    int r = blockIdx.x * 8 + (threadIdx.x >> 5);
    if (r >= ROWS) return;
    int lane = threadIdx.x & 31;
    int t = r / NODE_NUM;
    int node = idx[r];
    const float* srow = (g_cnt[t * NUM_NODES + node] < 2)
                      ? (x + (size_t)r * E_DIM)
                      : &g_S[((size_t)t * NUM_NODES + node) * E_DIM];
    const float* brow = bx + (size_t)node * E_DIM;
    float4 a0 = *(const float4*)(srow + lane * 4);
    float4 a1 = *(const float4*)(srow + 128 + lane * 4);
    float4 b0 = *(const float4*)(brow + lane * 4);
    float4 b1 = *(const float4*)(brow + 128 + lane * 4);
    float v[8] = { a0.x + b0.x, a0.y + b0.y, a0.z + b0.z, a0.w + b0.w,
                   a1.x + b1.x, a1.y + b1.y, a1.z + b1.z, a1.w + b1.w };
    float s1 = 0.f, s2 = 0.f;
    #pragma unroll
    for (int j = 0; j < 8; j++) { s1 += v[j]; s2 += v[j] * v[j]; }
    #pragma unroll
    for (int o = 16; o > 0; o >>= 1) {
        s1 += __shfl_xor_sync(0xffffffffu, s1, o);
        s2 += __shfl_xor_sync(0xffffffffu, s2, o);
    }
    float mu = s1 * (1.f / 256.f);
    float rs = rsqrtf(s2 * (1.f / 256.f) - mu * mu + LN_EPS);
    #pragma unroll
    for (int half_i = 0; half_i < 2; half_i++) {
        #pragma unroll
        for (int j = 0; j < 2; j++) {
            int c = half_i * 128 + lane * 4 + j * 2;
            float o0 = (v[half_i * 4 + j * 2 + 0] - mu) * rs * sc[c]     + bi[c];
            float o1 = (v[half_i * 4 + j * 2 + 1] - mu) * rs * sc[c + 1] + bi[c + 1];
            *(__half2*)&g_A0[(size_t)r * E_DIM + c] = __floats2half2_rn(o0, o1);
        }
    }
}

// ---------------- mma.sync fp16 GEMM, split-B: K' = 2K ----------------
// stream 0: A x B_hi; stream 1: A x B_lo. Accumulate fp32.
// EPI: 1 = bias+GELU -> fp16 out; 2 = bias -> fp32 out; 3 = bias+LN -> fp16 out (N==128)
#define ROWB 144            // padded smem row stride in bytes (72 fp16)
#define STG_BYTES 36864     // (128 rows A + 128 rows B) * 144
#define LNPAD 132           // fp32 staging row stride for EPI=3

template<int EPI>
__global__ void __launch_bounds__(256, 2) mma_gemm(
    const __half* __restrict__ A,
    const __half* __restrict__ Bhi, const __half* __restrict__ Blo,
    const float* __restrict__ bias,
    const float* __restrict__ lns, const float* __restrict__ lnb,
    __half* __restrict__ Ch, float* __restrict__ Cf,
    int M, int N, int K)
{
    extern __shared__ char smem[];
    const uint32_t sbase = smem_u32(smem);
    const int t = threadIdx.x, wid = t >> 5, lane = t & 31;
    const int wm = wid >> 2, wn = wid & 3;
    const int g = lane >> 2, tig = lane & 3;
    const int quad = lane >> 3, qr = lane & 7;
    const int bm = blockIdx.y * 128, bn = blockIdx.x * 128;
    const int kc = K >> 6;          // stages per stream
    const int nst = 2 * kc;

    const int lrow = t >> 3, lc = t & 7;

    auto load_stage = [&](int st) {
        int s = st % 3;
        int grp = st / kc;                       // 0,1 stream
        int kk = (st - grp * kc) << 6;
        const __half* As = A + kk;
        const __half* Bs = (grp ? Blo : Bhi) + kk;
        uint32_t Ab = sbase + s * STG_BYTES;
        uint32_t Bb = Ab + 128 * ROWB;
        #pragma unroll
        for (int i = 0; i < 4; i++) {
            int row = i * 32 + lrow;
            int grow = bm + row;
            int sz = (grow < M) ? 16 : 0;
            const __half* src = As + (size_t)((grow < M) ? grow : (M - 1)) * K + lc * 8;
            CP_ASYNC16(Ab + row * ROWB + lc * 16, src, sz);
        }
        #pragma unroll
        for (int i = 0; i < 4; i++) {
            int row = i * 32 + lrow;
            const __half* src = Bs + (size_t)(bn + row) * K + lc * 8;
            CP_ASYNC16_U(Bb + row * ROWB + lc * 16, src);
        }
    };

    float acc[4][4][4];
    #pragma unroll
    for (int a = 0; a < 4; a++)
        #pragma unroll
        for (int b = 0; b < 4; b++)
            #pragma unroll
            for (int c = 0; c < 4; c++) acc[a][b][c] = 0.f;

    load_stage(0); CP_COMMIT();
    load_stage(1); CP_COMMIT();

    for (int st = 0; st < nst; ++st) {
        CP_WAIT1();
        __syncthreads();
        if (st + 2 < nst) load_stage(st + 2);
        CP_COMMIT();
        int s = st % 3;
        uint32_t Ab = sbase + s * STG_BYTES;
        uint32_t Bb = Ab + 128 * ROWB;
        #pragma unroll
        for (int ks = 0; ks < 4; ks++) {
            int ch = ks * 2 + (quad >> 1);
            uint32_t a[4][4], b[2][4];
            #pragma unroll
            for (int mt = 0; mt < 4; mt++) {
                uint32_t ad = Ab + (uint32_t)(wm * 64 + mt * 16 + (quad & 1) * 8 + qr) * ROWB + ch * 16;
                LDMATRIX_X4(a[mt][0], a[mt][1], a[mt][2], a[mt][3], ad);
            }
            #pragma unroll
            for (int np = 0; np < 2; np++) {
                uint32_t ad = Bb + (uint32_t)(wn * 32 + np * 16 + (quad & 1) * 8 + qr) * ROWB + ch * 16;
                LDMATRIX_X4(b[np][0], b[np][1], b[np][2], b[np][3], ad);
            }
            #pragma unroll
            for (int mt = 0; mt < 4; mt++)
                #pragma unroll
                for (int nt = 0; nt < 4; nt++)
                    MMA16816(acc[mt][nt][0], acc[mt][nt][1], acc[mt][nt][2], acc[mt][nt][3],
                             a[mt][0], a[mt][1], a[mt][2], a[mt][3],
                             b[nt >> 1][nt & 1], b[nt >> 1][2 + (nt & 1)]);
        }
    }

    if (EPI == 3) {
        // ---- fused bias + LayerNorm(128) epilogue -> fp16 out ----
        float* sf = (float*)smem;   // [128][LNPAD] fp32 staging
        __syncthreads();
        #pragma unroll
        for (int mt = 0; mt < 4; mt++) {
            int lr0 = wm * 64 + mt * 16 + g;
            #pragma unroll
            for (int nt = 0; nt < 4; nt++) {
                int col = wn * 32 + nt * 8 + tig * 2;
                float bz0 = bias[col], bz1 = bias[col + 1];
                sf[lr0 * LNPAD + col]           = acc[mt][nt][0] + bz0;
                sf[lr0 * LNPAD + col + 1]       = acc[mt][nt][1] + bz1;
                sf[(lr0 + 8) * LNPAD + col]     = acc[mt][nt][2] + bz0;
                sf[(lr0 + 8) * LNPAD + col + 1] = acc[mt][nt][3] + bz1;
            }
        }
        __syncthreads();
        for (int rr = 0; rr < 16; rr++) {
            int lr = wid * 16 + rr;
            int grow = bm + lr;
            float v[4];
            #pragma unroll
            for (int j = 0; j < 4; j++) v[j] = sf[lr * LNPAD + lane * 4 + j];
            float s1 = v[0] + v[1] + v[2] + v[3];
            float s2 = v[0]*v[0] + v[1]*v[1] + v[2]*v[2] + v[3]*v[3];
            #pragma unroll
            for (int o = 16; o > 0; o >>= 1) {
                s1 += __shfl_xor_sync(0xffffffffu, s1, o);
                s2 += __shfl_xor_sync(0xffffffffu, s2, o);
            }
            float mu = s1 * (1.f / 128.f);
            float rs = rsqrtf(s2 * (1.f / 128.f) - mu * mu + LN_EPS);
            if (grow < M) {
                #pragma unroll
                for (int j = 0; j < 2; j++) {
                    int c = lane * 4 + j * 2;
                    float o0 = (v[j * 2 + 0] - mu) * rs * lns[c]     + lnb[c];
                    float o1 = (v[j * 2 + 1] - mu) * rs * lns[c + 1] + lnb[c + 1];
                    *(__half2*)&Ch[(size_t)grow * C_DIM + c] = __floats2half2_rn(o0, o1);
                }
            }
        }
    } else {
        #pragma unroll
        for (int mt = 0; mt < 4; mt++) {
            int r0 = bm + wm * 64 + mt * 16 + g;
            int r1 = r0 + 8;
            #pragma unroll
            for (int nt = 0; nt < 4; nt++) {
                int col = bn + wn * 32 + nt * 8 + tig * 2;
                float bz0 = bias[col], bz1 = bias[col + 1];
                float v0 = acc[mt][nt][0] + bz0, v1 = acc[mt][nt][1] + bz1;
                float v2 = acc[mt][nt][2] + bz0, v3 = acc[mt][nt][3] + bz1;
                if (EPI == 1) {
                    v0 = gelu_exact(v0); v1 = gelu_exact(v1);
                    v2 = gelu_exact(v2); v3 = gelu_exact(v3);
                }
                if (EPI == 2) {
                    if (r0 < M) *(float2*)&Cf[(size_t)r0 * N + col] = make_float2(v0, v1);
                    if (r1 < M) *(float2*)&Cf[(size_t)r1 * N + col] = make_float2(v2, v3);
                } else {
                    if (r0 < M)
                        *(__half2*)&Ch[(size_t)r0 * N + col] = __floats2half2_rn(v0, v1);
                    if (r1 < M)
                        *(__half2*)&Ch[(size_t)r1 * N + col] = __floats2half2_rn(v2, v3);
                }
            }
        }
    }
}

// ---------------- launcher ----------------
extern "C" void kernel_launch(void* const* d_in, const int* in_sizes, int n_in,
                              void* d_out, int out_size) {
    (void)in_sizes; (void)n_in; (void)out_size;
    const float* x          = (const float*)d_in[0];
    const float* batched_x  = (const float*)d_in[1];
    const int*   indices    = (const int*)  d_in[2];
    const float* ln_d_scale = (const float*)d_in[3];
    const float* ln_d_bias  = (const float*)d_in[4];
    const float* W1_d       = (const float*)d_in[5];
    const float* b1_d       = (const float*)d_in[6];
    const float* W2_d       = (const float*)d_in[7];
    const float* b2_d       = (const float*)d_in[8];
    const float* ln_u_scale = (const float*)d_in[9];
    const float* ln_u_bias  = (const float*)d_in[10];
    const float* W1_u       = (const float*)d_in[11];
    const float* b1_u       = (const float*)d_in[12];
    const float* W2_u       = (const float*)d_in[13];
    const float* b2_u       = (const float*)d_in[14];
    float* out = (float*)d_out;

    __half *a0, *h1, *gg, *h2;
    __half *w1dh, *w1dl, *w2dh, *w2dl, *w1uh, *w1ul, *w2uh, *w2ul;
    cudaGetSymbolAddress((void**)&a0, g_A0);
    cudaGetSymbolAddress((void**)&h1, g_H1);
    cudaGetSymbolAddress((void**)&gg, g_G);
    cudaGetSymbolAddress((void**)&h2, g_H2);
    cudaGetSymbolAddress((void**)&w1dh, g_w1dh); cudaGetSymbolAddress((void**)&w1dl, g_w1dl);
    cudaGetSymbolAddress((void**)&w2dh, g_w2dh); cudaGetSymbolAddress((void**)&w2dl, g_w2dl);
    cudaGetSymbolAddress((void**)&w1uh, g_w1uh); cudaGetSymbolAddress((void**)&w1ul, g_w1ul);
    cudaGetSymbolAddress((void**)&w2uh, g_w2uh); cudaGetSymbolAddress((void**)&w2ul, g_w2ul);

    const int DYN = 3 * STG_BYTES;   // 110592
    cudaFuncSetAttribute(mma_gemm<1>, cudaFuncAttributeMaxDynamicSharedMemorySize, DYN);
    cudaFuncSetAttribute(mma_gemm<2>, cudaFuncAttributeMaxDynamicSharedMemorySize, DYN);
    cudaFuncSetAttribute(mma_gemm<3>, cudaFuncAttributeMaxDynamicSharedMemorySize, DYN);

    // weight prep (coalesced transpose + fp16 split)
    dim3 tb(32, 8);
    k_wsplit<<<dim3(H_DIM / 32, E_DIM / 32), tb>>>(W1_d, w1dh, w1dl, E_DIM, H_DIM);
    k_wsplit<<<dim3(C_DIM / 32, H_DIM / 32), tb>>>(W2_d, w2dh, w2dl, H_DIM, C_DIM);
    k_wsplit<<<dim3(U_DIM / 32, C_DIM / 32), tb>>>(W1_u, w1uh, w1ul, C_DIM, U_DIM);
    k_wsplit<<<dim3(E_DIM / 32, U_DIM / 32), tb>>>(W2_u, w2uh, w2ul, U_DIM, E_DIM);

    // front-end (duplicate-aware)
    const int FB = (ROWS + 7) / 8;
    k_clr     <<<(T_STEPS * NUM_NODES + 255) / 256, 256>>>();
    k_count   <<<(ROWS + 255) / 256, 256>>>(indices);
    k_zero_dup<<<FB, 256>>>(indices);
    k_scat_dup<<<FB, 256>>>(x, indices);
    k_gather_ln<<<FB, 256>>>(x, batched_x, indices, ln_d_scale, ln_d_bias);

    // GEMM chain (fp16, split-B, 2 streams)
    mma_gemm<1><<<dim3(H_DIM / 128, MBLK), 256, DYN>>>(a0, w1dh, w1dl, b1_d,
                                                       nullptr, nullptr,
                                                       h1, nullptr, ROWS, H_DIM, E_DIM);
    mma_gemm<3><<<dim3(1, MBLK), 256, DYN>>>(h1, w2dh, w2dl, b2_d,
                                             ln_u_scale, ln_u_bias,
                                             gg, nullptr, ROWS, C_DIM, H_DIM);
    mma_gemm<1><<<dim3(U_DIM / 128, MBLK), 256, DYN>>>(gg, w1uh, w1ul, b1_u,
                                                       nullptr, nullptr,
                                                       h2, nullptr, ROWS, U_DIM, C_DIM);
    mma_gemm<2><<<dim3(E_DIM / 128, MBLK), 256, DYN>>>(h2, w2uh, w2ul, b2_u,
                                                       nullptr, nullptr,
                                                       nullptr, out, ROWS, E_DIM, U_DIM);
}